// round 14
// baseline (speedup 1.0000x reference)
#include <cuda_runtime.h>

#define ROWS   4096
#define NCOLS  16384
#define NVEC   4096            // float4 blocks per row
#define NPAIRS 8199
#define OUTROW 16398
#define BLOCK  256
#define GROUPS_TOTAL 4100      // group g -> cA(2g),cA(2g+1), cD(2g-1),cD(2g)
#define BLOCKS_X     2
#define GPT          8         // groups per thread
#define GPB          (GPT * BLOCK)   // 2048; tail 4096..4099 on block 1

// Window order: pair m reads x[2m-6+j], tap j pairs with DEC[7-j]
__device__ constexpr float CA_W[8] = {
     0.23037781330885523f,  0.7148465705525415f,   0.6308807679295904f,
    -0.02798376941698385f, -0.18703481171888114f,  0.030841381835986965f,
     0.032883011666982945f, -0.010597401784997278f };
__device__ constexpr float CD_W[8] = {
    -0.010597401784997278f, -0.032883011666982945f, 0.030841381835986965f,
     0.18703481171888114f,  -0.02798376941698385f, -0.6308807679295904f,
     0.7148465705525415f,   -0.23037781330885523f };

__device__ __forceinline__ float4 ldz(const float4* __restrict__ p, int j)
{
    if (j >= 0 && j < NVEC) return p[j];
    return make_float4(0.f, 0.f, 0.f, 0.f);
}

__global__ __launch_bounds__(BLOCK, 2)
void dwt_db4_kernel(const float* __restrict__ x, float* __restrict__ out)
{
    const int row = blockIdx.y;
    const int bx  = blockIdx.x;
    const int gb  = bx * GPB + threadIdx.x;          // first group of this thread
    const float4* __restrict__ xr4 =
        reinterpret_cast<const float4*>(x + (size_t)row * NCOLS);
    float* __restrict__ orow = out + (size_t)row * OUTROW;

    // ---- front-batched loads: 24 independent LDG.128 per thread ----
    float4 w0[GPT], w1[GPT], w2[GPT];
    if (bx == 0) {
        // only i==0, tid<2 can underrun -> guard just that iteration
        {
            const int g = gb;
            w0[0] = ldz(xr4, g - 2);
            w1[0] = ldz(xr4, g - 1);
            w2[0] = xr4[g];
        }
        #pragma unroll
        for (int i = 1; i < GPT; i++) {
            const int g = gb + i * BLOCK;
            w0[i] = xr4[g - 2];
            w1[i] = xr4[g - 1];
            w2[i] = xr4[g];
        }
    } else {
        #pragma unroll
        for (int i = 0; i < GPT; i++) {
            const int g = gb + i * BLOCK;            // g <= 4095 -> in range
            w0[i] = xr4[g - 2];
            w1[i] = xr4[g - 1];
            w2[i] = xr4[g];
        }
    }

    // ---- compute + store ----
    #pragma unroll
    for (int i = 0; i < GPT; i++) {
        const int g = gb + i * BLOCK;
        const float wv[12] = { w0[i].x, w0[i].y, w0[i].z, w0[i].w,
                               w1[i].x, w1[i].y, w1[i].z, w1[i].w,
                               w2[i].x, w2[i].y, w2[i].z, w2[i].w };
        float a0 = 0.f, a1 = 0.f, dm = 0.f, d0 = 0.f;
        #pragma unroll
        for (int j = 0; j < 8; j++) {
            a0 = fmaf(CA_W[j], wv[j + 2], a0);   // cA(2g)
            a1 = fmaf(CA_W[j], wv[j + 4], a1);   // cA(2g+1)
            dm = fmaf(CD_W[j], wv[j + 0], dm);   // cD(2g-1)
            d0 = fmaf(CD_W[j], wv[j + 2], d0);   // cD(2g)
        }
        // g <= 4095 here: cA pair always full; cD pair full unless g==0
        __stcs(reinterpret_cast<float2*>(orow + 2 * g), make_float2(a0, a1));
        if (bx != 0 || i != 0 || threadIdx.x != 0) {
            __stcs(reinterpret_cast<float2*>(orow + (NPAIRS - 1) + 2 * g),
                   make_float2(dm, d0));
        } else {
            __stcs(orow + NPAIRS, d0);           // g==0: only cD(0)
        }
    }

    // ---- tail groups 4096..4099 (last block, 4 threads) ----
    if (bx == BLOCKS_X - 1 && threadIdx.x < GROUPS_TOTAL - BLOCKS_X * GPB) {
        const int g = BLOCKS_X * GPB + threadIdx.x;  // 4096..4099
        const float4 t0 = ldz(xr4, g - 2);
        const float4 t1 = ldz(xr4, g - 1);
        const float4 t2 = ldz(xr4, g);
        const float wv[12] = { t0.x, t0.y, t0.z, t0.w,
                               t1.x, t1.y, t1.z, t1.w,
                               t2.x, t2.y, t2.z, t2.w };
        float a0 = 0.f, a1 = 0.f, dm = 0.f, d0 = 0.f;
        #pragma unroll
        for (int j = 0; j < 8; j++) {
            a0 = fmaf(CA_W[j], wv[j + 2], a0);
            a1 = fmaf(CA_W[j], wv[j + 4], a1);
            dm = fmaf(CD_W[j], wv[j + 0], dm);
            d0 = fmaf(CD_W[j], wv[j + 2], d0);
        }
        if (g < GROUPS_TOTAL - 1) {
            __stcs(reinterpret_cast<float2*>(orow + 2 * g), make_float2(a0, a1));
        } else {
            __stcs(orow + 2 * g, a0);                 // g=4099: only m=8198
        }
        __stcs(reinterpret_cast<float2*>(orow + (NPAIRS - 1) + 2 * g),
               make_float2(dm, d0));                  // g>=1 always
    }
}

extern "C" void kernel_launch(void* const* d_in, const int* in_sizes, int n_in,
                              void* d_out, int out_size)
{
    const float* x = (const float*)d_in[0];
    float* out = (float*)d_out;
    dim3 grid(BLOCKS_X, ROWS);
    dwt_db4_kernel<<<grid, BLOCK>>>(x, out);
}